// round 14
// baseline (speedup 1.0000x reference)
#include <cuda_runtime.h>
#include <cuda_bf16.h>
#include <math.h>

#define ATOMS_N 48
#define NSPEC 4
#define RAD_LEN 64
#define ANG_SUB 32
#define ANG_LEN 320
#define AEV_LEN 384
#define RCR_F 5.2f
#define RCA_F 3.5f
#define PI_F 3.14159265358979323846f
#define SQRT095_F 0.974679434f   /* sqrt(0.95) */
#define SQRT2_F   1.414213562f

__global__ __launch_bounds__(128, 11)
void aev_kernel(const float* __restrict__ coords,
                const float* __restrict__ EtaR,
                const float* __restrict__ ShfR,
                const float* __restrict__ EtaA,
                const float* __restrict__ Zeta,
                const float* __restrict__ ShfA,
                const float* __restrict__ ShfZ,
                const int*   __restrict__ species,
                float* __restrict__ out)
{
    __shared__ __align__(16) float sc[ATOMS_N * 3];
    __shared__ float4 rpack[ATOMS_N];   // (d, fcR*mask, spec_bits, -)
    __shared__ float4 apack[ATOMS_N];   // (dx, dy, dz, d/2)
    __shared__ float4 bpack[ATOMS_N];   // (ainv, sqrt2*fcA, spec_bits, -)
    __shared__ int    ncnt;
    __shared__ __align__(16) float acc[AEV_LEN];
    __shared__ float  shR[16], shA[4], czv[8], szv[8];
    __shared__ float  sP[3];  // etaR, etaA, zeta
    __shared__ float  sQ[4];  // Q_rad, deltaR, Q_ang, deltaA

    const int tid = threadIdx.x;
    const int m  = blockIdx.x / ATOMS_N;
    const int ci = blockIdx.x % ATOMS_N;

    // ---- coalesced loads (float4) + params + zero accumulator ----
    if (tid < 36)
        reinterpret_cast<float4*>(sc)[tid] =
            reinterpret_cast<const float4*>(coords + m * 144)[tid];
    int myspec = 0;
    if (tid < ATOMS_N) myspec = species[m * ATOMS_N + tid];
    if (tid >= 64 && tid < 80) shR[tid - 64] = ShfR[tid - 64];
    if (tid >= 80 && tid < 84) shA[tid - 80] = ShfA[tid - 80];
    if (tid >= 88 && tid < 96) {
        float v = ShfZ[tid - 88];
        czv[tid - 88] = cosf(v);
        szv[tid - 88] = sinf(v);
    }
    if (tid == 96) sP[0] = EtaR[0];
    if (tid == 97) sP[1] = EtaA[0];
    if (tid == 98) sP[2] = Zeta[0];
    if (tid == 99) ncnt = 0;
    acc[tid] = 0.0f; acc[tid + 128] = 0.0f; acc[tid + 256] = 0.0f;
    __syncthreads();

    // ---- parallel geometry: one atom per thread + atomic compaction ----
    if (tid < ATOMS_N) {
        const float cx = sc[3 * ci], cy = sc[3 * ci + 1], cz = sc[3 * ci + 2];
        float dx = sc[3 * tid]     - cx;
        float dy = sc[3 * tid + 1] - cy;
        float dz = sc[3 * tid + 2] - cz;
        float d  = sqrtf(dx * dx + dy * dy + dz * dz);

        bool own = (tid != ci);
        float fr = (own && d <= RCR_F) ? (0.5f * __cosf(d * (PI_F / RCR_F)) + 0.5f) : 0.0f;
        rpack[tid] = make_float4(d, fr, __int_as_float(myspec), 0.0f);

        if (own && d <= RCA_F) {
            float fa = 0.5f * __cosf(d * (PI_F / RCA_F)) + 0.5f;
            int p = atomicAdd(&ncnt, 1);
            apack[p] = make_float4(dx, dy, dz, 0.5f * d);
            bpack[p] = make_float4(SQRT095_F * __frcp_rn(fmaxf(d, 1e-8f)),
                                   SQRT2_F * fa,
                                   __int_as_float(myspec), 0.0f);
        }
    } else if (tid == 48 + 16) {   // tid 64: also did shR load pre-sync; any idle thread works
        // (placeholder - actual Q computed below by tid 112/113)
    }
    // recurrence constants (uniform shift grids): computed once per block
    if (tid == 112) {
        float dR = shR[1] - shR[0];
        sQ[0] = __expf(-2.0f * sP[0] * dR * dR);
        sQ[1] = dR;
    }
    if (tid == 113) {
        float dA = shA[1] - shA[0];
        sQ[2] = __expf(-2.0f * sP[1] * dA * dA);
        sQ[3] = dA;
    }
    __syncthreads();

    // ---- radial: atom-per-thread-pair, Gaussian recurrence (2 expf per 8 shifts) ----
    // Writes acc[0..64); angular writes acc[64..384) — disjoint, no barrier.
    if (tid < 96) {
        const int j = tid >> 1;
        const int h = tid & 1;          // shift half: r in [8h, 8h+8)
        float4 rp = rpack[j];
        if (rp.y != 0.0f) {
            const float er = sP[0];
            const float Q  = sQ[0];
            const float dR = sQ[1];
            const float s0 = shR[h << 3];
            float x = rp.x - s0;
            float e = 0.25f * rp.y * __expf(-er * x * x);
            float q = __expf(er * dR * (2.0f * x - dR));
            int base = (__float_as_int(rp.z) << 4) + (h << 3);
            #pragma unroll
            for (int r = 0; r < 8; r++) {
                atomicAdd(&acc[base + r], e);
                e *= q;
                q *= Q;
            }
        }
    }

    // ---- angular: 2 threads per pair (z-halves), hoisted constants,
    //      f2 via Gaussian recurrence (2 expf) + register rotate ----
    {
        const int lane = tid & 31;
        const int zh   = (lane & 1) << 2;   // z-half base: 0 or 4
        const int zo   = (lane >> 1) & 3;   // z rotation within half
        const int ar   = (lane >> 3) & 3;   // a rotation

        // Hoist loop-invariant shared loads (atomics below block auto-hoist).
        int   zvr[4], avr[4];
        float czr[4], szr[4];
        #pragma unroll
        for (int zi = 0; zi < 4; zi++) {
            int z = zh + ((zi + zo) & 3);
            zvr[zi] = z;
            czr[zi] = czv[z];
            szr[zi] = szv[z];
        }
        #pragma unroll
        for (int ai = 0; ai < 4; ai++) {
            avr[ai] = ((ai + ar) & 3) << 3;
        }
        const bool rb0 = (ar & 1);
        const bool rb1 = (ar & 2);

        const float etaA = sP[1];
        const float zeta = sP[2];
        const bool  z32  = (zeta == 32.0f);
        const float QA   = sQ[2];
        const float dA   = sQ[3];
        const float shA0 = shA[0];

        const int n     = ncnt;
        const int npair = (n * (n - 1)) >> 1;
        const float fn  = (float)(2 * n - 1);

        for (int q = (tid >> 1); q < npair; q += 64) {
            // closed-form upper-triangular decode with one-step fixup
            float disc = fn * fn - 8.0f * (float)q;
            int jj = (int)(0.5f * (fn - sqrtf(disc)));
            int off = (jj * (2 * n - 1 - jj)) >> 1;
            if (off > q) { jj--; off = (jj * (2 * n - 1 - jj)) >> 1; }
            else {
                int o2 = ((jj + 1) * (2 * n - 2 - jj)) >> 1;
                if (o2 <= q) { jj++; off = o2; }
            }
            int kk = jj + 1 + (q - off);

            float4 aj = apack[jj], ak = apack[kk];
            float4 bj = bpack[jj], bk = bpack[kk];

            float dot = aj.x * ak.x + aj.y * ak.y + aj.z * ak.z;
            float ca  = dot * bj.x * bk.x;
            float sa  = sqrtf(fmaxf(1.0f - ca * ca, 0.0f));
            float dm  = aj.w + ak.w;
            float fcj2 = bj.y * bk.y;

            int s1 = __float_as_int(bj.z), s2 = __float_as_int(bk.z);
            int lo = min(s1, s2), hi = max(s1, s2);
            int pidx = ((lo * (2 * NSPEC + 1 - lo)) >> 1) + (hi - lo);
            float* a0 = &acc[RAD_LEN + pidx * ANG_SUB];

            // f2 for the 4 ShfA values via recurrence: 2 expf instead of 4
            float xm = dm - shA0;
            float e2 = __expf(-etaA * xm * xm) * fcj2;
            float q2 = __expf(etaA * dA * (2.0f * xm - dA));
            float g0 = e2; e2 *= q2; q2 *= QA;
            float g1 = e2; e2 *= q2; q2 *= QA;
            float g2 = e2; e2 *= q2;
            float g3 = e2;
            // rotate left by ar (matches avr): f2r[ai] = g[(ai+ar)&3]
            float t0 = rb1 ? g2 : g0, t1 = rb1 ? g3 : g1;
            float t2 = rb1 ? g0 : g2, t3 = rb1 ? g1 : g3;
            float f2r[4];
            f2r[0] = rb0 ? t1 : t0;
            f2r[1] = rb0 ? t2 : t1;
            f2r[2] = rb0 ? t3 : t2;
            f2r[3] = rb0 ? t0 : t3;

            #pragma unroll
            for (int zi = 0; zi < 4; zi++) {
                float c = ca * czr[zi] + sa * szr[zi];
                float x = 0.5f + 0.5f * c;
                float f1;
                if (z32) {
                    float x2 = x * x, x4 = x2 * x2, x8 = x4 * x4, x16 = x8 * x8;
                    f1 = x16 * x16;
                } else {
                    f1 = __powf(x, zeta);
                }
                #pragma unroll
                for (int ai = 0; ai < 4; ai++) {
                    atomicAdd(&a0[avr[ai] + zvr[zi]], f1 * f2r[ai]);
                }
            }
        }
    }
    __syncthreads();

    // ---- coalesced output (float4) ----
    float* o = out + (size_t)blockIdx.x * AEV_LEN;
    if (tid < 96)
        reinterpret_cast<float4*>(o)[tid] =
            reinterpret_cast<const float4*>(acc)[tid];
}

extern "C" void kernel_launch(void* const* d_in, const int* in_sizes, int n_in,
                              void* d_out, int out_size) {
    const float* coords = (const float*)d_in[0];
    const float* EtaR   = (const float*)d_in[1];
    const float* ShfR   = (const float*)d_in[2];
    const float* EtaA   = (const float*)d_in[3];
    const float* Zeta   = (const float*)d_in[4];
    const float* ShfA   = (const float*)d_in[5];
    const float* ShfZ   = (const float*)d_in[6];
    const int*   spec   = (const int*)d_in[7];
    float* out = (float*)d_out;

    int M = in_sizes[0] / (ATOMS_N * 3);
    aev_kernel<<<M * ATOMS_N, 128>>>(coords, EtaR, ShfR, EtaA, Zeta, ShfA, ShfZ, spec, out);
}

// round 16
// speedup vs baseline: 1.1040x; 1.1040x over previous
#include <cuda_runtime.h>
#include <cuda_bf16.h>
#include <math.h>

#define ATOMS_N 48
#define NSPEC 4
#define RAD_LEN 64
#define ANG_SUB 32
#define ANG_LEN 320
#define AEV_LEN 384
#define RCR_F 5.2f
#define RCA_F 3.5f
#define PI_F 3.14159265358979323846f
#define SQRT095_F 0.974679434f   /* sqrt(0.95) */
#define SQRT2_F   1.414213562f

// closed-form upper-triangular decode with one-step fixup
#define PAIR_DECODE(qq, jj, kk)                                              \
    {                                                                        \
        float disc = fn * fn - 8.0f * (float)(qq);                           \
        jj = (int)(0.5f * (fn - sqrtf(disc)));                               \
        int off = (jj * (2 * n - 1 - jj)) >> 1;                              \
        if (off > (qq)) { jj--; off = (jj * (2 * n - 1 - jj)) >> 1; }        \
        else {                                                               \
            int o2 = ((jj + 1) * (2 * n - 2 - jj)) >> 1;                     \
            if (o2 <= (qq)) { jj++; off = o2; }                              \
        }                                                                    \
        kk = jj + 1 + ((qq) - off);                                          \
    }

__global__ __launch_bounds__(128, 11)
void aev_kernel(const float* __restrict__ coords,
                const float* __restrict__ EtaR,
                const float* __restrict__ ShfR,
                const float* __restrict__ EtaA,
                const float* __restrict__ Zeta,
                const float* __restrict__ ShfA,
                const float* __restrict__ ShfZ,
                const int*   __restrict__ species,
                float* __restrict__ out)
{
    __shared__ __align__(16) float sc[ATOMS_N * 3];
    __shared__ float4 rpack[ATOMS_N];   // (d, fcR*mask, spec_bits, -)
    __shared__ float4 apack[ATOMS_N];   // (dx, dy, dz, d/2)
    __shared__ float4 bpack[ATOMS_N];   // (ainv, sqrt2*fcA, spec_bits, -)
    __shared__ int    ncnt;
    __shared__ __align__(16) float acc[AEV_LEN];
    __shared__ float  shR[16], shA[4], czv[8], szv[8];
    __shared__ float  sP[3]; // etaR, etaA, zeta

    const int tid = threadIdx.x;
    const int m  = blockIdx.x / ATOMS_N;
    const int ci = blockIdx.x % ATOMS_N;

    // ---- coalesced loads (float4) + params + zero accumulator ----
    if (tid < 36)
        reinterpret_cast<float4*>(sc)[tid] =
            reinterpret_cast<const float4*>(coords + m * 144)[tid];
    int myspec = 0;
    if (tid < ATOMS_N) myspec = species[m * ATOMS_N + tid];
    if (tid >= 64 && tid < 80) shR[tid - 64] = ShfR[tid - 64];
    if (tid >= 80 && tid < 84) shA[tid - 80] = ShfA[tid - 80];
    if (tid >= 88 && tid < 96) {
        float v = ShfZ[tid - 88];
        czv[tid - 88] = cosf(v);
        szv[tid - 88] = sinf(v);
    }
    if (tid == 96) sP[0] = EtaR[0];
    if (tid == 97) sP[1] = EtaA[0];
    if (tid == 98) sP[2] = Zeta[0];
    if (tid == 99) ncnt = 0;
    acc[tid] = 0.0f; acc[tid + 128] = 0.0f; acc[tid + 256] = 0.0f;
    __syncthreads();

    // ---- parallel geometry: one atom per thread + atomic compaction ----
    if (tid < ATOMS_N) {
        const float cx = sc[3 * ci], cy = sc[3 * ci + 1], cz = sc[3 * ci + 2];
        float dx = sc[3 * tid]     - cx;
        float dy = sc[3 * tid + 1] - cy;
        float dz = sc[3 * tid + 2] - cz;
        float d  = sqrtf(dx * dx + dy * dy + dz * dz);

        bool own = (tid != ci);
        float fr = (own && d <= RCR_F) ? (0.5f * __cosf(d * (PI_F / RCR_F)) + 0.5f) : 0.0f;
        rpack[tid] = make_float4(d, fr, __int_as_float(myspec), 0.0f);

        if (own && d <= RCA_F) {
            float fa = 0.5f * __cosf(d * (PI_F / RCA_F)) + 0.5f;
            int p = atomicAdd(&ncnt, 1);
            apack[p] = make_float4(dx, dy, dz, 0.5f * d);
            bpack[p] = make_float4(SQRT095_F * __frcp_rn(fmaxf(d, 1e-8f)),
                                   SQRT2_F * fa,
                                   __int_as_float(myspec), 0.0f);
        }
    }
    __syncthreads();

    // ---- radial: atom-centric, 1 LDS.128 per atom, mask folded into fcR ----
    // Writes acc[0..64); angular writes acc[64..384) — disjoint, no barrier.
    {
        const int r  = tid & 15;
        const int j0 = tid >> 4;
        const float er = sP[0];
        const float sh = shR[r];
        #pragma unroll
        for (int i = 0; i < 6; i++) {
            int j = j0 + (i << 3);
            float4 rp = rpack[j];
            float t = rp.x - sh;
            float e = 0.25f * __expf(-er * t * t) * rp.y;
            if (rp.y != 0.0f)
                atomicAdd(&acc[(__float_as_int(rp.z) << 4) + r], e);
        }
    }

    // ---- angular: 2 threads per pair (z-halves), hoisted constants,
    //      TWO pairs interleaved per iteration for ILP ----
    {
        const int lane = tid & 31;
        const int zh   = (lane & 1) << 2;   // z-half base: 0 or 4
        const int zo   = (lane >> 1) & 3;   // z rotation within half
        const int ar   = (lane >> 3) & 3;   // a rotation

        // Hoist loop-invariant shared loads (atomics below block auto-hoist).
        int   zvr[4], avr[4];
        float czr[4], szr[4], shar[4];
        #pragma unroll
        for (int zi = 0; zi < 4; zi++) {
            int z = zh + ((zi + zo) & 3);
            zvr[zi] = z;
            czr[zi] = czv[z];
            szr[zi] = szv[z];
        }
        #pragma unroll
        for (int ai = 0; ai < 4; ai++) {
            int a = (ai + ar) & 3;
            avr[ai] = a << 3;
            shar[ai] = shA[a];
        }

        const float etaA = sP[1];
        const float zeta = sP[2];
        const bool  z32  = (zeta == 32.0f);

        const int n     = ncnt;
        const int npair = (n * (n - 1)) >> 1;
        const float fn  = (float)(2 * n - 1);

        for (int q = (tid >> 1); q < npair; q += 128) {
            const int  qB   = q + 64;
            const bool has2 = (qB < npair);

            // --- decode both pairs (B guarded; dummy slots 0,1 if absent) ---
            int jjA, kkA;
            PAIR_DECODE(q, jjA, kkA);
            int jjB = 0, kkB = 1;
            if (has2) PAIR_DECODE(qB, jjB, kkB);

            // --- issue all 8 LDS.128 together (independent) ---
            float4 ajA = apack[jjA], akA = apack[kkA];
            float4 bjA = bpack[jjA], bkA = bpack[kkA];
            float4 ajB = apack[jjB], akB = apack[kkB];
            float4 bjB = bpack[jjB], bkB = bpack[kkB];

            // --- head A ---
            float dotA = ajA.x * akA.x + ajA.y * akA.y + ajA.z * akA.z;
            float caA  = dotA * bjA.x * bkA.x;
            float saA  = sqrtf(fmaxf(1.0f - caA * caA, 0.0f));
            float dmA  = ajA.w + akA.w;
            float fcA2 = bjA.y * bkA.y;
            int s1A = __float_as_int(bjA.z), s2A = __float_as_int(bkA.z);
            int loA = min(s1A, s2A), hiA = max(s1A, s2A);
            float* a0A = &acc[RAD_LEN + (((loA * (2 * NSPEC + 1 - loA)) >> 1) + (hiA - loA)) * ANG_SUB];

            // --- head B (computed unconditionally on dummy data; cheap) ---
            float dotB = ajB.x * akB.x + ajB.y * akB.y + ajB.z * akB.z;
            float caB  = dotB * bjB.x * bkB.x;
            float saB  = sqrtf(fmaxf(1.0f - caB * caB, 0.0f));
            float dmB  = ajB.w + akB.w;
            float fcB2 = bjB.y * bkB.y;
            int s1B = __float_as_int(bjB.z), s2B = __float_as_int(bkB.z);
            int loB = min(s1B, s2B), hiB = max(s1B, s2B);
            float* a0B = &acc[RAD_LEN + (((loB * (2 * NSPEC + 1 - loB)) >> 1) + (hiB - loB)) * ANG_SUB];

            // --- f2 for both (8 independent expf) ---
            float f2rA[4], f2rB[4];
            #pragma unroll
            for (int ai = 0; ai < 4; ai++) {
                float tA = dmA - shar[ai];
                float tB = dmB - shar[ai];
                f2rA[ai] = __expf(-etaA * tA * tA) * fcA2;
                f2rB[ai] = __expf(-etaA * tB * tB) * fcB2;
            }

            // --- z-chains A ---
            #pragma unroll
            for (int zi = 0; zi < 4; zi++) {
                float c = caA * czr[zi] + saA * szr[zi];
                float x = 0.5f + 0.5f * c;
                float f1;
                if (z32) {
                    float x2 = x * x, x4 = x2 * x2, x8 = x4 * x4, x16 = x8 * x8;
                    f1 = x16 * x16;
                } else {
                    f1 = __powf(x, zeta);
                }
                #pragma unroll
                for (int ai = 0; ai < 4; ai++)
                    atomicAdd(&a0A[avr[ai] + zvr[zi]], f1 * f2rA[ai]);
            }

            // --- z-chains B (guarded) ---
            if (has2) {
                #pragma unroll
                for (int zi = 0; zi < 4; zi++) {
                    float c = caB * czr[zi] + saB * szr[zi];
                    float x = 0.5f + 0.5f * c;
                    float f1;
                    if (z32) {
                        float x2 = x * x, x4 = x2 * x2, x8 = x4 * x4, x16 = x8 * x8;
                        f1 = x16 * x16;
                    } else {
                        f1 = __powf(x, zeta);
                    }
                    #pragma unroll
                    for (int ai = 0; ai < 4; ai++)
                        atomicAdd(&a0B[avr[ai] + zvr[zi]], f1 * f2rB[ai]);
                }
            }
        }
    }
    __syncthreads();

    // ---- coalesced output (float4) ----
    float* o = out + (size_t)blockIdx.x * AEV_LEN;
    if (tid < 96)
        reinterpret_cast<float4*>(o)[tid] =
            reinterpret_cast<const float4*>(acc)[tid];
}

extern "C" void kernel_launch(void* const* d_in, const int* in_sizes, int n_in,
                              void* d_out, int out_size) {
    const float* coords = (const float*)d_in[0];
    const float* EtaR   = (const float*)d_in[1];
    const float* ShfR   = (const float*)d_in[2];
    const float* EtaA   = (const float*)d_in[3];
    const float* Zeta   = (const float*)d_in[4];
    const float* ShfA   = (const float*)d_in[5];
    const float* ShfZ   = (const float*)d_in[6];
    const int*   spec   = (const int*)d_in[7];
    float* out = (float*)d_out;

    int M = in_sizes[0] / (ATOMS_N * 3);
    aev_kernel<<<M * ATOMS_N, 128>>>(coords, EtaR, ShfR, EtaA, Zeta, ShfA, ShfZ, spec, out);
}